// round 12
// baseline (speedup 1.0000x reference)
#include <cuda_runtime.h>
#include <cuda_bf16.h>
#include <cstdint>

// AdaptiveTokenMixer: out[b,n,:] = sum_k alpha[b,n,k] * x[b,n+k,:]
// Shapes fixed: B=8, N=4096, d=256, K=8.
//
// R12 design: lightweight multi-tile pipeline. SEG=32 rows/block as 4 tiles
// of 8 rows; x streamed through a 3-buffer (24 KB) cp.async ring with depth-1
// overlap (block T+2 staged while tile T computes). One wait + one barrier
// per tile. Window spans buffers T and T+1 (both drained by the schedule).

constexpr int K_OFF = 8;               // kernel window
constexpr int D4    = 64;              // d / 4 (float4 columns)
constexpr int NRT   = 8;               // rows per tile / staging block
constexpr int TILES = 4;               // tiles per CTA
constexpr int SEG   = NRT * TILES;     // 32 output rows per CTA
constexpr int BUFS  = 3;               // smem ring depth (24 KB)
constexpr int NTHR  = 128;
constexpr int DTN   = 40;              // staged dt/mask entries (>= SEG+7)

// valid_mask dtype probe (JAX bool may arrive as uint8 / int32 / float32).
// lengths >= N/2 guarantees mask[0..3] of batch 0 are all True:
//   uint8:   byte[1] == 1
//   float32: byte[1] == 0, byte[3] == 0x3f
//   int32:   byte[1] == 0, byte[3] == 0x00
__device__ __forceinline__ int probe_mask_mode(const unsigned char* vm) {
    if (vm[1] != 0) return 0;           // uint8
    if (vm[3] == 0x3f) return 2;        // float32
    return 1;                           // int32
}

__device__ __forceinline__ bool mask_at(const unsigned char* vm, int idx, int mode) {
    if (mode == 0) return vm[idx] != 0;
    if (mode == 1) return reinterpret_cast<const int*>(vm)[idx] != 0;
    return reinterpret_cast<const float*>(vm)[idx] != 0.0f;
}

__device__ __forceinline__ void cp_async16(uint32_t dst_smem, const void* src, int src_bytes) {
    asm volatile("cp.async.cg.shared.global [%0], [%1], 16, %2;\n"
                 :: "r"(dst_smem), "l"(src), "r"(src_bytes));
}

__global__ __launch_bounds__(NTHR, 6) void atm_kernel(
    const float* __restrict__ x,
    const float* __restrict__ dt,
    const unsigned char* __restrict__ vm,
    const float* __restrict__ w,
    const float* __restrict__ beta,
    float* __restrict__ out,
    int N)
{
    __shared__ float4 s_x[BUFS * NRT][D4];   // 24 KB ring of 8-row blocks
    __shared__ float4 s_alpha[SEG][2];       // 8 alphas per row as two float4
    __shared__ float  s_dt[DTN];
    __shared__ int    s_vm[DTN];

    const int b    = blockIdx.y;
    const int seg0 = blockIdx.x * SEG;       // first output row of this CTA
    const int tid  = threadIdx.x;

    const float4* __restrict__ xb =
        reinterpret_cast<const float4*>(x) + (size_t)b * N * D4;
    const uint32_t s_base = (uint32_t)__cvta_generic_to_shared(&s_x[0][0]);

    // Stage 8-row block J into ring buffer J%3, one commit group per block.
#define STAGE_BLOCK(J)                                                         \
    {                                                                          \
        _Pragma("unroll")                                                      \
        for (int i = 0; i < NRT * D4 / NTHR; i++) {        /* 4 per thread */  \
            const int idx = tid + i * NTHR;                                    \
            const int row = idx >> 6;                                          \
            const int col = idx & (D4 - 1);                                    \
            const int n   = seg0 + (J) * NRT + row;                            \
            const int ns  = (n < N) ? n : (N - 1);                             \
            const int nb  = (n < N) ? 16 : 0;                                  \
            const int di  = (((J) % BUFS) * NRT + row) * D4 + col;             \
            cp_async16(s_base + (uint32_t)di * 16u,                            \
                       xb + (size_t)ns * D4 + col, nb);                        \
        }                                                                      \
        asm volatile("cp.async.commit_group;\n" ::: "memory");                 \
    }

    // -------- Prologue: blocks 0,1 in flight; dt/mask wavefront; alphas ------
    STAGE_BLOCK(0)
    STAGE_BLOCK(1)

    if (tid < DTN) {
        const int mmode = probe_mask_mode(vm);
        const int n  = seg0 + tid;
        const int ns = (n < N) ? n : (N - 1);
        s_dt[tid] = dt[(size_t)b * N + ns];
        s_vm[tid] = (n < N) && mask_at(vm, b * N + ns, mmode) ? 1 : 0;
    }
    __syncthreads();

    if (tid < SEG) {
        float wv[K_OFF];
        #pragma unroll
        for (int k = 0; k < K_OFF; k++) wv[k] = w[k];
        float wm = wv[0];
        #pragma unroll
        for (int k = 1; k < K_OFF; k++) wm = fmaxf(wm, wv[k]);
        float wsum = 0.f;
        #pragma unroll
        for (int k = 0; k < K_OFF; k++) { wv[k] = __expf(wv[k] - wm); wsum += wv[k]; }
        const float winv = 1.f / wsum;
        const float bsig = 1.f / (1.f + __expf(-beta[0]));

        const int   v0  = s_vm[tid];
        const float dtn = s_dt[tid];

        float sc[K_OFF];
        int   cv[K_OFF];
        #pragma unroll
        for (int k = 0; k < K_OFF; k++) {
            const int cnd = v0 & s_vm[tid + k];          // s_vm=0 beyond N
            const float td = (k == 0) ? 0.f : fmaxf(s_dt[tid + k] - dtn, 0.f);
            cv[k] = cnd;
            sc[k] = cnd ? -td : -1e9f;
        }
        float m = sc[0];
        #pragma unroll
        for (int k = 1; k < K_OFF; k++) m = fmaxf(m, sc[k]);
        float th[K_OFF];
        float es = 0.f;
        #pragma unroll
        for (int k = 0; k < K_OFF; k++) { th[k] = __expf(sc[k] - m); es += th[k]; }
        const float einv = 1.f / es;

        float a[K_OFF];
        float asum = 0.f;
        #pragma unroll
        for (int k = 0; k < K_OFF; k++) {
            const float v = bsig * (wv[k] * winv) + (1.f - bsig) * (th[k] * einv);
            a[k] = cv[k] ? v : 0.f;
            asum += a[k];
        }
        const float ainv = 1.f / fmaxf(asum, 1e-8f);
        #pragma unroll
        for (int k = 0; k < K_OFF; k++) a[k] *= ainv;
        s_alpha[tid][0] = make_float4(a[0], a[1], a[2], a[3]);
        s_alpha[tid][1] = make_float4(a[4], a[5], a[6], a[7]);
    }

    // -------- Pipelined tile loop ---------------------------------------------
    const int c = tid & (D4 - 1);
    const int g = tid >> 6;                   // 2 groups -> 4 rows each per tile

    float4* __restrict__ ocol =
        reinterpret_cast<float4*>(out) + (size_t)b * N * D4 + c;

    // Tile T: window rows T*8+g*4 .. T*8+g*4+10 span staged blocks T and T+1.
    // Schedule: both are drained by wait_group(0); block T+2 staged afterwards
    // overlaps with this tile's compute (depth-1 pipeline). The syncthreads
    // also guarantees tile T-1's reads finished before its buffer is reused.
#define DO_TILE(T, DOSTAGE)                                                    \
    {                                                                          \
        asm volatile("cp.async.wait_group 0;\n" ::: "memory");                 \
        __syncthreads();                                                       \
        if (DOSTAGE) STAGE_BLOCK((T) + 2)                                      \
        const int s0 = ((T) % BUFS) * NRT;                                     \
        const int s1 = (((T) + 1) % BUFS) * NRT;                               \
        const int gofs = g * 4;                                                \
        float4 win[11];                                                        \
        _Pragma("unroll")                                                      \
        for (int k = 0; k < 11; k++) {                                         \
            const int off  = gofs + k;              /* 0..14 */                \
            const int slot = ((off >> 3) ? s1 : s0) + (off & 7);               \
            win[k] = s_x[slot][c];                                             \
        }                                                                      \
        _Pragma("unroll")                                                      \
        for (int r = 0; r < 4; r++) {                                          \
            const int row = (T) * NRT + gofs + r;   /* block-local 0..31 */    \
            const float4 a03 = s_alpha[row][0];                                \
            const float4 a47 = s_alpha[row][1];                                \
            const float al[K_OFF] = { a03.x, a03.y, a03.z, a03.w,              \
                                      a47.x, a47.y, a47.z, a47.w };            \
            float4 acc = make_float4(0.f, 0.f, 0.f, 0.f);                      \
            _Pragma("unroll")                                                  \
            for (int k = 0; k < K_OFF; k++) {                                  \
                const float  a = al[k];                                        \
                const float4 v = win[r + k];                                   \
                acc.x = fmaf(a, v.x, acc.x);                                   \
                acc.y = fmaf(a, v.y, acc.y);                                   \
                acc.z = fmaf(a, v.z, acc.z);                                   \
                acc.w = fmaf(a, v.w, acc.w);                                   \
            }                                                                  \
            ocol[(size_t)(seg0 + row) * D4] = acc;                             \
        }                                                                      \
    }

    DO_TILE(0, 1)   // stages block 2
    DO_TILE(1, 1)   // stages block 3
    DO_TILE(2, 1)   // stages block 4
    DO_TILE(3, 0)

#undef DO_TILE
#undef STAGE_BLOCK
}

extern "C" void kernel_launch(void* const* d_in, const int* in_sizes, int n_in,
                              void* d_out, int out_size)
{
    // metadata order: x [B,N,d] f32, delta_times [B,N] f32, valid_mask [B,N],
    //                 w [8] f32, beta [1] f32 ; output [B,N,d] f32
    const float*         x    = (const float*)d_in[0];
    const float*         dt   = (const float*)d_in[1];
    const unsigned char* vm   = (const unsigned char*)d_in[2];
    const float*         w    = (const float*)d_in[3];
    const float*         beta = (const float*)d_in[4];
    float*               out  = (float*)d_out;

    const int N = 4096;                       // fixed by problem
    const int BN = in_sizes[1];               // B*N
    const int B = BN / N;                     // 8

    dim3 grid(N / SEG, B);                    // 128 x 8 = 1024 blocks
    atm_kernel<<<grid, NTHR>>>(x, dt, vm, w, beta, out, N);
}

// round 13
// speedup vs baseline: 1.0022x; 1.0022x over previous
#include <cuda_runtime.h>
#include <cuda_bf16.h>
#include <cstdint>

// AdaptiveTokenMixer: out[b,n,:] = sum_k alpha[b,n,k] * x[b,n+k,:]
// Shapes fixed: B=8, N=4096, d=256, K=8.
//
// R13 design: refined R11 pipeline. SEG=64 rows/CTA as 4 tiles of 16 rows;
// x streamed through a 4-buffer (64 KB) cp.async ring. Prologue stages
// blocks 0,1,2; tile T: wait_group(1) [drains blocks <= T+1, leaves 1-2
// groups in flight], ONE __syncthreads, stage block T+3, compute. The fill
// latency is paid once per CTA; steady-state compute always has its data.

constexpr int K_OFF = 8;               // kernel window
constexpr int D4    = 64;              // d / 4 (float4 columns)
constexpr int NRT   = 16;              // rows per tile / staging block
constexpr int TILES = 4;               // tiles per CTA
constexpr int SEG   = NRT * TILES;     // 64 output rows per CTA
constexpr int SBLK  = TILES + 1;       // staging blocks 0..4 (rows 0..79)
constexpr int BUFS  = 4;               // smem ring depth (64 KB)
constexpr int NTHR  = 128;
constexpr int DTN   = 72;              // staged dt/mask entries (>= SEG+7)

// valid_mask dtype probe (JAX bool may arrive as uint8 / int32 / float32).
// lengths >= N/2 guarantees mask[0..3] of batch 0 are all True:
//   uint8:   byte[1] == 1
//   float32: byte[1] == 0, byte[3] == 0x3f
//   int32:   byte[1] == 0, byte[3] == 0x00
__device__ __forceinline__ int probe_mask_mode(const unsigned char* vm) {
    if (vm[1] != 0) return 0;           // uint8
    if (vm[3] == 0x3f) return 2;        // float32
    return 1;                           // int32
}

__device__ __forceinline__ bool mask_at(const unsigned char* vm, int idx, int mode) {
    if (mode == 0) return vm[idx] != 0;
    if (mode == 1) return reinterpret_cast<const int*>(vm)[idx] != 0;
    return reinterpret_cast<const float*>(vm)[idx] != 0.0f;
}

__device__ __forceinline__ void cp_async16(uint32_t dst_smem, const void* src, int src_bytes) {
    asm volatile("cp.async.cg.shared.global [%0], [%1], 16, %2;\n"
                 :: "r"(dst_smem), "l"(src), "r"(src_bytes));
}

__global__ __launch_bounds__(NTHR, 3) void atm_kernel(
    const float* __restrict__ x,
    const float* __restrict__ dt,
    const unsigned char* __restrict__ vm,
    const float* __restrict__ w,
    const float* __restrict__ beta,
    float* __restrict__ out,
    int N)
{
    __shared__ float4 s_x[BUFS * NRT][D4];   // 64 KB ring of 16-row blocks
    __shared__ float4 s_alpha[SEG][2];       // 8 alphas per row as two float4
    __shared__ float  s_dt[DTN];
    __shared__ int    s_vm[DTN];

    const int b    = blockIdx.y;
    const int seg0 = blockIdx.x * SEG;       // first output row of this CTA
    const int tid  = threadIdx.x;

    const float4* __restrict__ xb =
        reinterpret_cast<const float4*>(x) + (size_t)b * N * D4;
    const uint32_t s_base = (uint32_t)__cvta_generic_to_shared(&s_x[0][0]);

    // Stage 16-row block J into ring buffer J%4, one commit group per block.
#define STAGE_BLOCK(J)                                                         \
    {                                                                          \
        _Pragma("unroll")                                                      \
        for (int i = 0; i < NRT * D4 / NTHR; i++) {        /* 8 per thread */  \
            const int idx = tid + i * NTHR;                                    \
            const int row = idx >> 6;                                          \
            const int col = idx & (D4 - 1);                                    \
            const int n   = seg0 + (J) * NRT + row;                            \
            const int ns  = (n < N) ? n : (N - 1);                             \
            const int nb  = (n < N) ? 16 : 0;                                  \
            const int di  = (((J) & (BUFS - 1)) * NRT + row) * D4 + col;       \
            cp_async16(s_base + (uint32_t)di * 16u,                            \
                       xb + (size_t)ns * D4 + col, nb);                        \
        }                                                                      \
        asm volatile("cp.async.commit_group;\n" ::: "memory");                 \
    }

    // -------- Prologue: blocks 0,1,2 in flight; dt/mask wavefront; alphas ----
    STAGE_BLOCK(0)
    STAGE_BLOCK(1)
    STAGE_BLOCK(2)

    if (tid < DTN) {
        const int mmode = probe_mask_mode(vm);
        const int n  = seg0 + tid;
        const int ns = (n < N) ? n : (N - 1);
        s_dt[tid] = dt[(size_t)b * N + ns];
        s_vm[tid] = (n < N) && mask_at(vm, b * N + ns, mmode) ? 1 : 0;
    }
    __syncthreads();

    if (tid < SEG) {
        float wv[K_OFF];
        #pragma unroll
        for (int k = 0; k < K_OFF; k++) wv[k] = w[k];
        float wm = wv[0];
        #pragma unroll
        for (int k = 1; k < K_OFF; k++) wm = fmaxf(wm, wv[k]);
        float wsum = 0.f;
        #pragma unroll
        for (int k = 0; k < K_OFF; k++) { wv[k] = __expf(wv[k] - wm); wsum += wv[k]; }
        const float winv = 1.f / wsum;
        const float bsig = 1.f / (1.f + __expf(-beta[0]));

        const int   v0  = s_vm[tid];
        const float dtn = s_dt[tid];

        float sc[K_OFF];
        int   cv[K_OFF];
        #pragma unroll
        for (int k = 0; k < K_OFF; k++) {
            const int cnd = v0 & s_vm[tid + k];          // s_vm=0 beyond N
            const float td = (k == 0) ? 0.f : fmaxf(s_dt[tid + k] - dtn, 0.f);
            cv[k] = cnd;
            sc[k] = cnd ? -td : -1e9f;
        }
        float m = sc[0];
        #pragma unroll
        for (int k = 1; k < K_OFF; k++) m = fmaxf(m, sc[k]);
        float th[K_OFF];
        float es = 0.f;
        #pragma unroll
        for (int k = 0; k < K_OFF; k++) { th[k] = __expf(sc[k] - m); es += th[k]; }
        const float einv = 1.f / es;

        float a[K_OFF];
        float asum = 0.f;
        #pragma unroll
        for (int k = 0; k < K_OFF; k++) {
            const float v = bsig * (wv[k] * winv) + (1.f - bsig) * (th[k] * einv);
            a[k] = cv[k] ? v : 0.f;
            asum += a[k];
        }
        const float ainv = 1.f / fmaxf(asum, 1e-8f);
        #pragma unroll
        for (int k = 0; k < K_OFF; k++) a[k] *= ainv;
        s_alpha[tid][0] = make_float4(a[0], a[1], a[2], a[3]);
        s_alpha[tid][1] = make_float4(a[4], a[5], a[6], a[7]);
    }

    // -------- Pipelined tile loop --------------------------------------------
    const int c = tid & (D4 - 1);
    const int g = tid >> 6;                   // 2 groups of 8 rows per tile

    float4* __restrict__ ocol =
        reinterpret_cast<float4*>(out) + (size_t)b * N * D4 + c;

    // Tile T window rows (local): T*16 + g*8 + k, k=0..14.
    //   g=0: all 15 rows in buffer T.
    //   g=1: k=0..7 in buffer T, k=8..14 in buffer T+1.
    // Schedule per tile: wait_group(W) -> sync -> stage T+3 -> compute.
    //   wait_group(1) leaves only the most recent commit pending, so blocks
    //   <= T+1 are complete (FIFO). The sync also proves tile T-1's reads of
    //   buffer (T+3)%4 = (T-1)%4 are done before re-staging it.
#define DO_TILE(T, WAITN, DOSTAGE)                                             \
    {                                                                          \
        asm volatile("cp.async.wait_group %0;\n" :: "n"(WAITN) : "memory");    \
        __syncthreads();                                                       \
        if (DOSTAGE) STAGE_BLOCK((T) + 3)                                      \
        const int bT  = ((T) & (BUFS - 1)) * NRT;                              \
        const int bT1 = (((T) + 1) & (BUFS - 1)) * NRT;                        \
        const int gofs = g * 8;                                                \
        float4 win[15];                                                        \
        _Pragma("unroll")                                                      \
        for (int k = 0; k < 15; k++) {                                         \
            const int lr = gofs + k;                                           \
            win[k] = (lr < NRT) ? s_x[bT + lr][c] : s_x[bT1 + (lr - NRT)][c];  \
        }                                                                      \
        _Pragma("unroll")                                                      \
        for (int r = 0; r < 8; r++) {                                          \
            const int row = (T) * NRT + gofs + r;   /* block-local 0..63 */    \
            const float4 a03 = s_alpha[row][0];                                \
            const float4 a47 = s_alpha[row][1];                                \
            const float al[K_OFF] = { a03.x, a03.y, a03.z, a03.w,              \
                                      a47.x, a47.y, a47.z, a47.w };            \
            float4 acc = make_float4(0.f, 0.f, 0.f, 0.f);                      \
            _Pragma("unroll")                                                  \
            for (int k = 0; k < K_OFF; k++) {                                  \
                const float  a = al[k];                                        \
                const float4 v = win[r + k];                                   \
                acc.x = fmaf(a, v.x, acc.x);                                   \
                acc.y = fmaf(a, v.y, acc.y);                                   \
                acc.z = fmaf(a, v.z, acc.z);                                   \
                acc.w = fmaf(a, v.w, acc.w);                                   \
            }                                                                  \
            ocol[(size_t)(seg0 + row) * D4] = acc;                             \
        }                                                                      \
    }

    // Commit-group FIFO audit (groups == staged blocks, in order):
    //  tile 0: pending {0,1,2}; wait(1) -> 0,1 done (2 may fly); stage 3
    //  tile 1: pending {2,3};   wait(1) -> 2 done   (3 may fly); stage 4
    //  tile 2: pending {3,4};   wait(1) -> 3 done   (4 may fly)
    //  tile 3: pending {4};     wait(0) -> 4 done
    DO_TILE(0, 1, 1)
    DO_TILE(1, 1, 1)
    DO_TILE(2, 1, 0)
    DO_TILE(3, 0, 0)

#undef DO_TILE
#undef STAGE_BLOCK
}

extern "C" void kernel_launch(void* const* d_in, const int* in_sizes, int n_in,
                              void* d_out, int out_size)
{
    // metadata order: x [B,N,d] f32, delta_times [B,N] f32, valid_mask [B,N],
    //                 w [8] f32, beta [1] f32 ; output [B,N,d] f32
    const float*         x    = (const float*)d_in[0];
    const float*         dt   = (const float*)d_in[1];
    const unsigned char* vm   = (const unsigned char*)d_in[2];
    const float*         w    = (const float*)d_in[3];
    const float*         beta = (const float*)d_in[4];
    float*               out  = (float*)d_out;

    const int N = 4096;                       // fixed by problem
    const int BN = in_sizes[1];               // B*N
    const int B = BN / N;                     // 8

    dim3 grid(N / SEG, B);                    // 64 x 8 = 512 blocks
    atm_kernel<<<grid, NTHR>>>(x, dt, vm, w, beta, out, N);
}

// round 14
// speedup vs baseline: 1.0243x; 1.0221x over previous
#include <cuda_runtime.h>
#include <cuda_bf16.h>
#include <cstdint>

// AdaptiveTokenMixer: out[b,n,:] = sum_k alpha[b,n,k] * x[b,n+k,:]
// Shapes fixed: B=8, N=4096, d=256, K=8.
//
// R14 design: small-footprint pipeline = R12's shape + R13's schedule.
// SEG=32 rows/CTA as 4 tiles of 8 rows; x streamed through a 4-buffer
// 16 KB cp.async ring. Prologue stages blocks 0,1,2; tile T does
// wait_group(1) [drains blocks <= T+1, leaves T+2 in flight], ONE sync,
// stages block T+3 into buffer (T+3)%4 (disjoint from the read buffers
// T%4,(T+1)%4), then computes. ~18 KB smem + ~64 regs -> 8 CTAs/SM:
// first variant with BOTH pipeline overlap and ~50% occupancy.

constexpr int K_OFF = 8;               // kernel window
constexpr int D4    = 64;              // d / 4 (float4 columns)
constexpr int NRT   = 8;               // rows per tile / staging block
constexpr int TILES = 4;               // tiles per CTA
constexpr int SEG   = NRT * TILES;     // 32 output rows per CTA
constexpr int BUFS  = 4;               // smem ring depth (16 KB)
constexpr int NTHR  = 128;
constexpr int DTN   = 40;              // staged dt/mask entries (>= SEG+7)

// valid_mask dtype probe (JAX bool may arrive as uint8 / int32 / float32).
// lengths >= N/2 guarantees mask[0..3] of batch 0 are all True:
//   uint8:   byte[1] == 1
//   float32: byte[1] == 0, byte[3] == 0x3f
//   int32:   byte[1] == 0, byte[3] == 0x00
__device__ __forceinline__ int probe_mask_mode(const unsigned char* vm) {
    if (vm[1] != 0) return 0;           // uint8
    if (vm[3] == 0x3f) return 2;        // float32
    return 1;                           // int32
}

__device__ __forceinline__ bool mask_at(const unsigned char* vm, int idx, int mode) {
    if (mode == 0) return vm[idx] != 0;
    if (mode == 1) return reinterpret_cast<const int*>(vm)[idx] != 0;
    return reinterpret_cast<const float*>(vm)[idx] != 0.0f;
}

__device__ __forceinline__ void cp_async16(uint32_t dst_smem, const void* src, int src_bytes) {
    asm volatile("cp.async.cg.shared.global [%0], [%1], 16, %2;\n"
                 :: "r"(dst_smem), "l"(src), "r"(src_bytes));
}

__global__ __launch_bounds__(NTHR, 8) void atm_kernel(
    const float* __restrict__ x,
    const float* __restrict__ dt,
    const unsigned char* __restrict__ vm,
    const float* __restrict__ w,
    const float* __restrict__ beta,
    float* __restrict__ out,
    int N)
{
    __shared__ float4 s_x[BUFS * NRT][D4];   // 16 KB ring of 8-row blocks
    __shared__ float4 s_alpha[SEG][2];       // 8 alphas per row as two float4
    __shared__ float  s_dt[DTN];
    __shared__ int    s_vm[DTN];

    const int b    = blockIdx.y;
    const int seg0 = blockIdx.x * SEG;       // first output row of this CTA
    const int tid  = threadIdx.x;

    const float4* __restrict__ xb =
        reinterpret_cast<const float4*>(x) + (size_t)b * N * D4;
    const uint32_t s_base = (uint32_t)__cvta_generic_to_shared(&s_x[0][0]);

    // Stage 8-row block J into ring buffer J%4, one commit group per block.
#define STAGE_BLOCK(J)                                                         \
    {                                                                          \
        _Pragma("unroll")                                                      \
        for (int i = 0; i < NRT * D4 / NTHR; i++) {        /* 4 per thread */  \
            const int idx = tid + i * NTHR;                                    \
            const int row = idx >> 6;                                          \
            const int col = idx & (D4 - 1);                                    \
            const int n   = seg0 + (J) * NRT + row;                            \
            const int ns  = (n < N) ? n : (N - 1);                             \
            const int nb  = (n < N) ? 16 : 0;                                  \
            const int di  = (((J) & (BUFS - 1)) * NRT + row) * D4 + col;       \
            cp_async16(s_base + (uint32_t)di * 16u,                            \
                       xb + (size_t)ns * D4 + col, nb);                        \
        }                                                                      \
        asm volatile("cp.async.commit_group;\n" ::: "memory");                 \
    }

    // -------- Prologue: blocks 0,1,2 in flight; dt/mask wavefront; alphas ----
    STAGE_BLOCK(0)
    STAGE_BLOCK(1)
    STAGE_BLOCK(2)

    if (tid < DTN) {
        const int mmode = probe_mask_mode(vm);
        const int n  = seg0 + tid;
        const int ns = (n < N) ? n : (N - 1);
        s_dt[tid] = dt[(size_t)b * N + ns];
        s_vm[tid] = (n < N) && mask_at(vm, b * N + ns, mmode) ? 1 : 0;
    }
    __syncthreads();

    if (tid < SEG) {
        float wv[K_OFF];
        #pragma unroll
        for (int k = 0; k < K_OFF; k++) wv[k] = w[k];
        float wm = wv[0];
        #pragma unroll
        for (int k = 1; k < K_OFF; k++) wm = fmaxf(wm, wv[k]);
        float wsum = 0.f;
        #pragma unroll
        for (int k = 0; k < K_OFF; k++) { wv[k] = __expf(wv[k] - wm); wsum += wv[k]; }
        const float winv = 1.f / wsum;
        const float bsig = 1.f / (1.f + __expf(-beta[0]));

        const int   v0  = s_vm[tid];
        const float dtn = s_dt[tid];

        float sc[K_OFF];
        int   cv[K_OFF];
        #pragma unroll
        for (int k = 0; k < K_OFF; k++) {
            const int cnd = v0 & s_vm[tid + k];          // s_vm=0 beyond N
            const float td = (k == 0) ? 0.f : fmaxf(s_dt[tid + k] - dtn, 0.f);
            cv[k] = cnd;
            sc[k] = cnd ? -td : -1e9f;
        }
        float m = sc[0];
        #pragma unroll
        for (int k = 1; k < K_OFF; k++) m = fmaxf(m, sc[k]);
        float th[K_OFF];
        float es = 0.f;
        #pragma unroll
        for (int k = 0; k < K_OFF; k++) { th[k] = __expf(sc[k] - m); es += th[k]; }
        const float einv = 1.f / es;

        float a[K_OFF];
        float asum = 0.f;
        #pragma unroll
        for (int k = 0; k < K_OFF; k++) {
            const float v = bsig * (wv[k] * winv) + (1.f - bsig) * (th[k] * einv);
            a[k] = cv[k] ? v : 0.f;
            asum += a[k];
        }
        const float ainv = 1.f / fmaxf(asum, 1e-8f);
        #pragma unroll
        for (int k = 0; k < K_OFF; k++) a[k] *= ainv;
        s_alpha[tid][0] = make_float4(a[0], a[1], a[2], a[3]);
        s_alpha[tid][1] = make_float4(a[4], a[5], a[6], a[7]);
    }

    // -------- Pipelined tile loop --------------------------------------------
    const int c = tid & (D4 - 1);
    const int g = tid >> 6;                   // 2 groups of 4 rows per tile

    float4* __restrict__ ocol =
        reinterpret_cast<float4*>(out) + (size_t)b * N * D4 + c;

    // Tile T window rows (local): T*8 + g*4 + k, k=0..10 — spans staged
    // blocks T (rows 0..7) and T+1 (rows 8..14 → local 0..6).
    // Per tile: wait_group(W) -> ONE sync -> stage T+3 -> compute.
    //   wait_group(1) leaves only the newest commit pending, so blocks
    //   <= T+1 are complete (FIFO). Buffer (T+3)%4 being staged is disjoint
    //   from read buffers T%4 and (T+1)%4; the sync proves tile T-1's reads
    //   of buffer (T+3)%4 = (T-1)%4 finished before the re-stage.
#define DO_TILE(T, WAITN, DOSTAGE)                                             \
    {                                                                          \
        asm volatile("cp.async.wait_group %0;\n" :: "n"(WAITN) : "memory");    \
        __syncthreads();                                                       \
        if (DOSTAGE) STAGE_BLOCK((T) + 3)                                      \
        const int bT  = ((T) & (BUFS - 1)) * NRT;                              \
        const int bT1 = (((T) + 1) & (BUFS - 1)) * NRT;                        \
        const int gofs = g * 4;                                                \
        float4 win[11];                                                        \
        _Pragma("unroll")                                                      \
        for (int k = 0; k < 11; k++) {                                         \
            const int lr = gofs + k;                      /* 0..10 or 4..14 */ \
            win[k] = (lr < NRT) ? s_x[bT + lr][c] : s_x[bT1 + (lr - NRT)][c];  \
        }                                                                      \
        _Pragma("unroll")                                                      \
        for (int r = 0; r < 4; r++) {                                          \
            const int row = (T) * NRT + gofs + r;   /* block-local 0..31 */    \
            const float4 a03 = s_alpha[row][0];                                \
            const float4 a47 = s_alpha[row][1];                                \
            const float al[K_OFF] = { a03.x, a03.y, a03.z, a03.w,              \
                                      a47.x, a47.y, a47.z, a47.w };            \
            float4 acc = make_float4(0.f, 0.f, 0.f, 0.f);                      \
            _Pragma("unroll")                                                  \
            for (int k = 0; k < K_OFF; k++) {                                  \
                const float  a = al[k];                                        \
                const float4 v = win[r + k];                                   \
                acc.x = fmaf(a, v.x, acc.x);                                   \
                acc.y = fmaf(a, v.y, acc.y);                                   \
                acc.z = fmaf(a, v.z, acc.z);                                   \
                acc.w = fmaf(a, v.w, acc.w);                                   \
            }                                                                  \
            ocol[(size_t)(seg0 + row) * D4] = acc;                             \
        }                                                                      \
    }

    // Commit-group FIFO audit (groups == staged blocks, in order):
    //  tile 0: pending {0,1,2}; wait(1) -> 0,1 done (2 may fly); stage 3
    //  tile 1: pending {2,3};   wait(1) -> 2 done   (3 may fly); stage 4
    //  tile 2: pending {3,4};   wait(1) -> 3 done   (4 may fly)
    //  tile 3: pending {4};     wait(0) -> 4 done
    DO_TILE(0, 1, 1)
    DO_TILE(1, 1, 1)
    DO_TILE(2, 1, 0)
    DO_TILE(3, 0, 0)

#undef DO_TILE
#undef STAGE_BLOCK
}

extern "C" void kernel_launch(void* const* d_in, const int* in_sizes, int n_in,
                              void* d_out, int out_size)
{
    // metadata order: x [B,N,d] f32, delta_times [B,N] f32, valid_mask [B,N],
    //                 w [8] f32, beta [1] f32 ; output [B,N,d] f32
    const float*         x    = (const float*)d_in[0];
    const float*         dt   = (const float*)d_in[1];
    const unsigned char* vm   = (const unsigned char*)d_in[2];
    const float*         w    = (const float*)d_in[3];
    const float*         beta = (const float*)d_in[4];
    float*               out  = (float*)d_out;

    const int N = 4096;                       // fixed by problem
    const int BN = in_sizes[1];               // B*N
    const int B = BN / N;                     // 8

    dim3 grid(N / SEG, B);                    // 128 x 8 = 1024 blocks
    atm_kernel<<<grid, NTHR>>>(x, dt, vm, w, beta, out, N);
}

// round 15
// speedup vs baseline: 1.0718x; 1.0463x over previous
#include <cuda_runtime.h>
#include <cuda_bf16.h>
#include <cstdint>

// AdaptiveTokenMixer: out[b,n,:] = sum_k alpha[b,n,k] * x[b,n+k,:]
// Shapes fixed: B=8, N=4096, d=256, K=8.
//
// R15 design: longest-serial-strip, single-wave, barrier-free main loop.
//  - grid 512 CTAs (64 rows each) -> ONE wave, all CTAs co-resident: no
//    wave transition, no tail.
//  - thread owns one float4 column of a 32-row strip; x via direct LDG
//    rolling ring of depth 14 (prefetch distance 7 iters ~ 300 cyc >= L2
//    hit latency). No smem round-trip for x (minimal LSU op budget).
//  - alphas for all 64 rows computed once in an overlapped prologue;
//    main loop has zero barriers: 2 LDS (alpha) + 1 LDG + 32 FFMA + 1 STG.

constexpr int K_OFF = 8;               // kernel window
constexpr int D4    = 64;              // d / 4 (float4 columns)
constexpr int RG    = 32;              // rows per thread strip
constexpr int G     = 2;               // strips per CTA
constexpr int NR    = RG * G;          // 64 rows per CTA
constexpr int RING  = 14;              // register ring depth (prefetch 6-7)
constexpr int NTHR  = 128;
constexpr int DTN   = 72;              // staged dt/mask entries (>= NR+7)

// valid_mask dtype probe (JAX bool may arrive as uint8 / int32 / float32).
// lengths >= N/2 guarantees mask[0..3] of batch 0 are all True:
//   uint8:   byte[1] == 1
//   float32: byte[1] == 0, byte[3] == 0x3f
//   int32:   byte[1] == 0, byte[3] == 0x00
__device__ __forceinline__ int probe_mask_mode(const unsigned char* vm) {
    if (vm[1] != 0) return 0;           // uint8
    if (vm[3] == 0x3f) return 2;        // float32
    return 1;                           // int32
}

__device__ __forceinline__ bool mask_at(const unsigned char* vm, int idx, int mode) {
    if (mode == 0) return vm[idx] != 0;
    if (mode == 1) return reinterpret_cast<const int*>(vm)[idx] != 0;
    return reinterpret_cast<const float*>(vm)[idx] != 0.0f;
}

__global__ __launch_bounds__(NTHR, 6) void atm_kernel(
    const float* __restrict__ x,
    const float* __restrict__ dt,
    const unsigned char* __restrict__ vm,
    const float* __restrict__ w,
    const float* __restrict__ beta,
    float* __restrict__ out,
    int N)
{
    __shared__ float4 s_alpha[NR][2];     // 8 alphas per row as two float4
    __shared__ float  s_dt[DTN];
    __shared__ int    s_vm[DTN];

    const int b   = blockIdx.y;
    const int n0  = blockIdx.x * NR;
    const int tid = threadIdx.x;

    // -------- Ring prefill (issued FIRST; overlaps the whole prologue) ------
    const int c = tid & (D4 - 1);
    const int g = tid >> 6;
    const int rbase = n0 + g * RG;

    const float4* __restrict__ xcol =
        reinterpret_cast<const float4*>(x) + (size_t)b * N * D4 + c;
    float4* __restrict__ ocol =
        reinterpret_cast<float4*>(out) + (size_t)b * N * D4 + c;

    const float4 zero4 = make_float4(0.f, 0.f, 0.f, 0.f);
    float4 win[RING];
    #pragma unroll
    for (int k = 0; k < RING; k++) {
        const int n = rbase + k;
        win[k] = (n < N) ? xcol[(size_t)n * D4] : zero4;
    }

    // -------- dt/mask parallel wavefront into smem ---------------------------
    if (tid < DTN) {
        const int mmode = probe_mask_mode(vm);
        const int n  = n0 + tid;
        const int ns = (n < N) ? n : (N - 1);
        s_dt[tid] = dt[(size_t)b * N + ns];
        s_vm[tid] = (n < N) && mask_at(vm, b * N + ns, mmode) ? 1 : 0;
    }
    __syncthreads();

    // -------- Alpha softmax for all 64 rows (smem/ALU only) ------------------
    if (tid < NR) {
        float wv[K_OFF];
        #pragma unroll
        for (int k = 0; k < K_OFF; k++) wv[k] = w[k];
        float wm = wv[0];
        #pragma unroll
        for (int k = 1; k < K_OFF; k++) wm = fmaxf(wm, wv[k]);
        float wsum = 0.f;
        #pragma unroll
        for (int k = 0; k < K_OFF; k++) { wv[k] = __expf(wv[k] - wm); wsum += wv[k]; }
        const float winv = 1.f / wsum;
        const float bsig = 1.f / (1.f + __expf(-beta[0]));

        const int   v0  = s_vm[tid];
        const float dtn = s_dt[tid];

        float sc[K_OFF];
        int   cv[K_OFF];
        #pragma unroll
        for (int k = 0; k < K_OFF; k++) {
            const int cnd = v0 & s_vm[tid + k];          // s_vm=0 beyond N
            const float td = (k == 0) ? 0.f : fmaxf(s_dt[tid + k] - dtn, 0.f);
            cv[k] = cnd;
            sc[k] = cnd ? -td : -1e9f;
        }
        float m = sc[0];
        #pragma unroll
        for (int k = 1; k < K_OFF; k++) m = fmaxf(m, sc[k]);
        float th[K_OFF];
        float es = 0.f;
        #pragma unroll
        for (int k = 0; k < K_OFF; k++) { th[k] = __expf(sc[k] - m); es += th[k]; }
        const float einv = 1.f / es;

        float a[K_OFF];
        float asum = 0.f;
        #pragma unroll
        for (int k = 0; k < K_OFF; k++) {
            const float v = bsig * (wv[k] * winv) + (1.f - bsig) * (th[k] * einv);
            a[k] = cv[k] ? v : 0.f;
            asum += a[k];
        }
        const float ainv = 1.f / fmaxf(asum, 1e-8f);
        #pragma unroll
        for (int k = 0; k < K_OFF; k++) a[k] *= ainv;
        s_alpha[tid][0] = make_float4(a[0], a[1], a[2], a[3]);
        s_alpha[tid][1] = make_float4(a[4], a[5], a[6], a[7]);
    }
    __syncthreads();    // last barrier — main loop below is barrier-free

    // -------- Main loop: 32 serial rows, rolling ring, no barriers -----------
    #pragma unroll
    for (int r = 0; r < RG; r++) {
        const int row = g * RG + r;
        const float4 a03 = s_alpha[row][0];
        const float4 a47 = s_alpha[row][1];
        const float al[K_OFF] = { a03.x, a03.y, a03.z, a03.w,
                                  a47.x, a47.y, a47.z, a47.w };

        float4 acc = zero4;
        #pragma unroll
        for (int k = 0; k < K_OFF; k++) {
            const float  a = al[k];
            const float4 v = win[(r + k) % RING];
            acc.x = fmaf(a, v.x, acc.x);
            acc.y = fmaf(a, v.y, acc.y);
            acc.z = fmaf(a, v.z, acc.z);
            acc.w = fmaf(a, v.w, acc.w);
        }
        ocol[(size_t)(rbase + r) * D4] = acc;

        // Refill slot just consumed at k=0 with row rbase+r+RING.
        // Last row needed: rbase+RG+6 -> refill while r+RING <= RG+6.
        if (r + RING <= RG + K_OFF - 2) {
            const int nl = rbase + r + RING;
            win[r % RING] = (nl < N) ? xcol[(size_t)nl * D4] : zero4;
        }
    }
}

extern "C" void kernel_launch(void* const* d_in, const int* in_sizes, int n_in,
                              void* d_out, int out_size)
{
    // metadata order: x [B,N,d] f32, delta_times [B,N] f32, valid_mask [B,N],
    //                 w [8] f32, beta [1] f32 ; output [B,N,d] f32
    const float*         x    = (const float*)d_in[0];
    const float*         dt   = (const float*)d_in[1];
    const unsigned char* vm   = (const unsigned char*)d_in[2];
    const float*         w    = (const float*)d_in[3];
    const float*         beta = (const float*)d_in[4];
    float*               out  = (float*)d_out;

    const int N = 4096;                       // fixed by problem
    const int BN = in_sizes[1];               // B*N
    const int B = BN / N;                     // 8

    dim3 grid(N / NR, B);                     // 64 x 8 = 512 CTAs: one wave
    atm_kernel<<<grid, NTHR>>>(x, dt, vm, w, beta, out, N);
}

// round 16
// speedup vs baseline: 1.1575x; 1.0800x over previous
#include <cuda_runtime.h>
#include <cuda_bf16.h>
#include <cstdint>

// AdaptiveTokenMixer: out[b,n,:] = sum_k alpha[b,n,k] * x[b,n+k,:]
// Shapes fixed: B=8, N=4096, d=256, K=8.
//
// R15 design: longest-serial-strip, single-wave, barrier-free main loop.
//  - grid 512 CTAs (64 rows each) -> ONE wave, all CTAs co-resident: no
//    wave transition, no tail.
//  - thread owns one float4 column of a 32-row strip; x via direct LDG
//    rolling ring of depth 14 (prefetch distance 7 iters ~ 300 cyc >= L2
//    hit latency). No smem round-trip for x (minimal LSU op budget).
//  - alphas for all 64 rows computed once in an overlapped prologue;
//    main loop has zero barriers: 2 LDS (alpha) + 1 LDG + 32 FFMA + 1 STG.

constexpr int K_OFF = 8;               // kernel window
constexpr int D4    = 64;              // d / 4 (float4 columns)
constexpr int RG    = 32;              // rows per thread strip
constexpr int G     = 2;               // strips per CTA
constexpr int NR    = RG * G;          // 64 rows per CTA
constexpr int RING  = 14;              // register ring depth (prefetch 6-7)
constexpr int NTHR  = 128;
constexpr int DTN   = 72;              // staged dt/mask entries (>= NR+7)

// valid_mask dtype probe (JAX bool may arrive as uint8 / int32 / float32).
// lengths >= N/2 guarantees mask[0..3] of batch 0 are all True:
//   uint8:   byte[1] == 1
//   float32: byte[1] == 0, byte[3] == 0x3f
//   int32:   byte[1] == 0, byte[3] == 0x00
__device__ __forceinline__ int probe_mask_mode(const unsigned char* vm) {
    if (vm[1] != 0) return 0;           // uint8
    if (vm[3] == 0x3f) return 2;        // float32
    return 1;                           // int32
}

__device__ __forceinline__ bool mask_at(const unsigned char* vm, int idx, int mode) {
    if (mode == 0) return vm[idx] != 0;
    if (mode == 1) return reinterpret_cast<const int*>(vm)[idx] != 0;
    return reinterpret_cast<const float*>(vm)[idx] != 0.0f;
}

__global__ __launch_bounds__(NTHR, 6) void atm_kernel(
    const float* __restrict__ x,
    const float* __restrict__ dt,
    const unsigned char* __restrict__ vm,
    const float* __restrict__ w,
    const float* __restrict__ beta,
    float* __restrict__ out,
    int N)
{
    __shared__ float4 s_alpha[NR][2];     // 8 alphas per row as two float4
    __shared__ float  s_dt[DTN];
    __shared__ int    s_vm[DTN];

    const int b   = blockIdx.y;
    const int n0  = blockIdx.x * NR;
    const int tid = threadIdx.x;

    // -------- Ring prefill (issued FIRST; overlaps the whole prologue) ------
    const int c = tid & (D4 - 1);
    const int g = tid >> 6;
    const int rbase = n0 + g * RG;

    const float4* __restrict__ xcol =
        reinterpret_cast<const float4*>(x) + (size_t)b * N * D4 + c;
    float4* __restrict__ ocol =
        reinterpret_cast<float4*>(out) + (size_t)b * N * D4 + c;

    const float4 zero4 = make_float4(0.f, 0.f, 0.f, 0.f);
    float4 win[RING];
    #pragma unroll
    for (int k = 0; k < RING; k++) {
        const int n = rbase + k;
        win[k] = (n < N) ? xcol[(size_t)n * D4] : zero4;
    }

    // -------- dt/mask parallel wavefront into smem ---------------------------
    if (tid < DTN) {
        const int mmode = probe_mask_mode(vm);
        const int n  = n0 + tid;
        const int ns = (n < N) ? n : (N - 1);
        s_dt[tid] = dt[(size_t)b * N + ns];
        s_vm[tid] = (n < N) && mask_at(vm, b * N + ns, mmode) ? 1 : 0;
    }
    __syncthreads();

    // -------- Alpha softmax for all 64 rows (smem/ALU only) ------------------
    if (tid < NR) {
        float wv[K_OFF];
        #pragma unroll
        for (int k = 0; k < K_OFF; k++) wv[k] = w[k];
        float wm = wv[0];
        #pragma unroll
        for (int k = 1; k < K_OFF; k++) wm = fmaxf(wm, wv[k]);
        float wsum = 0.f;
        #pragma unroll
        for (int k = 0; k < K_OFF; k++) { wv[k] = __expf(wv[k] - wm); wsum += wv[k]; }
        const float winv = 1.f / wsum;
        const float bsig = 1.f / (1.f + __expf(-beta[0]));

        const int   v0  = s_vm[tid];
        const float dtn = s_dt[tid];

        float sc[K_OFF];
        int   cv[K_OFF];
        #pragma unroll
        for (int k = 0; k < K_OFF; k++) {
            const int cnd = v0 & s_vm[tid + k];          // s_vm=0 beyond N
            const float td = (k == 0) ? 0.f : fmaxf(s_dt[tid + k] - dtn, 0.f);
            cv[k] = cnd;
            sc[k] = cnd ? -td : -1e9f;
        }
        float m = sc[0];
        #pragma unroll
        for (int k = 1; k < K_OFF; k++) m = fmaxf(m, sc[k]);
        float th[K_OFF];
        float es = 0.f;
        #pragma unroll
        for (int k = 0; k < K_OFF; k++) { th[k] = __expf(sc[k] - m); es += th[k]; }
        const float einv = 1.f / es;

        float a[K_OFF];
        float asum = 0.f;
        #pragma unroll
        for (int k = 0; k < K_OFF; k++) {
            const float v = bsig * (wv[k] * winv) + (1.f - bsig) * (th[k] * einv);
            a[k] = cv[k] ? v : 0.f;
            asum += a[k];
        }
        const float ainv = 1.f / fmaxf(asum, 1e-8f);
        #pragma unroll
        for (int k = 0; k < K_OFF; k++) a[k] *= ainv;
        s_alpha[tid][0] = make_float4(a[0], a[1], a[2], a[3]);
        s_alpha[tid][1] = make_float4(a[4], a[5], a[6], a[7]);
    }
    __syncthreads();    // last barrier — main loop below is barrier-free

    // -------- Main loop: 32 serial rows, rolling ring, no barriers -----------
    #pragma unroll
    for (int r = 0; r < RG; r++) {
        const int row = g * RG + r;
        const float4 a03 = s_alpha[row][0];
        const float4 a47 = s_alpha[row][1];
        const float al[K_OFF] = { a03.x, a03.y, a03.z, a03.w,
                                  a47.x, a47.y, a47.z, a47.w };

        float4 acc = zero4;
        #pragma unroll
        for (int k = 0; k < K_OFF; k++) {
            const float  a = al[k];
            const float4 v = win[(r + k) % RING];
            acc.x = fmaf(a, v.x, acc.x);
            acc.y = fmaf(a, v.y, acc.y);
            acc.z = fmaf(a, v.z, acc.z);
            acc.w = fmaf(a, v.w, acc.w);
        }
        ocol[(size_t)(rbase + r) * D4] = acc;

        // Refill slot just consumed at k=0 with row rbase+r+RING.
        // Last row needed: rbase+RG+6 -> refill while r+RING <= RG+6.
        if (r + RING <= RG + K_OFF - 2) {
            const int nl = rbase + r + RING;
            win[r % RING] = (nl < N) ? xcol[(size_t)nl * D4] : zero4;
        }
    }
}

extern "C" void kernel_launch(void* const* d_in, const int* in_sizes, int n_in,
                              void* d_out, int out_size)
{
    // metadata order: x [B,N,d] f32, delta_times [B,N] f32, valid_mask [B,N],
    //                 w [8] f32, beta [1] f32 ; output [B,N,d] f32
    const float*         x    = (const float*)d_in[0];
    const float*         dt   = (const float*)d_in[1];
    const unsigned char* vm   = (const unsigned char*)d_in[2];
    const float*         w    = (const float*)d_in[3];
    const float*         beta = (const float*)d_in[4];
    float*               out  = (float*)d_out;

    const int N = 4096;                       // fixed by problem
    const int BN = in_sizes[1];               // B*N
    const int B = BN / N;                     // 8

    dim3 grid(N / NR, B);                     // 64 x 8 = 512 CTAs: one wave
    atm_kernel<<<grid, NTHR>>>(x, dt, vm, w, beta, out, N);
}